// round 1
// baseline (speedup 1.0000x reference)
#include <cuda_runtime.h>
#include <math.h>

#define S_LEN  2048
#define D_MODEL 1024
#define NHEAD  16
#define HDIM   64

// Scratch (device globals: allocation-free, zero-initialized at module load).
// g_qk upper triangle is NEVER written -> stays zero across graph replays (deterministic).
static __device__ float g_q[S_LEN * D_MODEL];
static __device__ float g_k[S_LEN * D_MODEL];
static __device__ float g_v[S_LEN * D_MODEL];
static __device__ float g_qk[(size_t)NHEAD * S_LEN * S_LEN];
static __device__ float g_L[NHEAD * S_LEN];
static __device__ float g_c[NHEAD * HDIM];
static __device__ float g_z[S_LEN * D_MODEL];

// ---------------------------------------------------------------------------
// NT GEMM with bias: C[M,N] = A[M,K] * B[N,K]^T + bias[N]
// 128x128 tile, BK=8, 256 threads, 8x8 per thread.
// Requires M%128==0, N%128==0, K%8==0.
// ---------------------------------------------------------------------------
__global__ __launch_bounds__(256)
void sgemm_nt_bias(const float* __restrict__ A, const float* __restrict__ B,
                   const float* __restrict__ bias, float* __restrict__ C,
                   int K, int lda, int ldb, int ldc)
{
    __shared__ float As[8][128];
    __shared__ float Bs[8][128];
    const int tid  = threadIdx.x;
    const int tx   = tid & 15;
    const int ty   = tid >> 4;
    const int row0 = blockIdx.y << 7;
    const int col0 = blockIdx.x << 7;
    const int lrow = tid >> 1;
    const int lk   = (tid & 1) << 2;

    const float* Ap = A + (size_t)(row0 + lrow) * lda + lk;
    const float* Bp = B + (size_t)(col0 + lrow) * ldb + lk;

    float acc[8][8];
#pragma unroll
    for (int i = 0; i < 8; i++)
#pragma unroll
        for (int j = 0; j < 8; j++) acc[i][j] = 0.f;

    for (int k0 = 0; k0 < K; k0 += 8) {
        float4 av = *(const float4*)(Ap + k0);
        float4 bv = *(const float4*)(Bp + k0);
        As[lk + 0][lrow] = av.x; As[lk + 1][lrow] = av.y;
        As[lk + 2][lrow] = av.z; As[lk + 3][lrow] = av.w;
        Bs[lk + 0][lrow] = bv.x; Bs[lk + 1][lrow] = bv.y;
        Bs[lk + 2][lrow] = bv.z; Bs[lk + 3][lrow] = bv.w;
        __syncthreads();
#pragma unroll
        for (int kk = 0; kk < 8; kk++) {
            float a[8], b[8];
            *(float4*)&a[0] = *(const float4*)&As[kk][(ty << 3)];
            *(float4*)&a[4] = *(const float4*)&As[kk][(ty << 3) + 4];
            *(float4*)&b[0] = *(const float4*)&Bs[kk][(tx << 3)];
            *(float4*)&b[4] = *(const float4*)&Bs[kk][(tx << 3) + 4];
#pragma unroll
            for (int i = 0; i < 8; i++)
#pragma unroll
                for (int j = 0; j < 8; j++)
                    acc[i][j] = fmaf(a[i], b[j], acc[i][j]);
        }
        __syncthreads();
    }

    float bb[8];
    *(float4*)&bb[0] = *(const float4*)&bias[col0 + (tx << 3)];
    *(float4*)&bb[4] = *(const float4*)&bias[col0 + (tx << 3) + 4];
#pragma unroll
    for (int i = 0; i < 8; i++) {
        float* Cp = C + (size_t)(row0 + (ty << 3) + i) * ldc + col0 + (tx << 3);
        float4 o0 = make_float4(acc[i][0] + bb[0], acc[i][1] + bb[1],
                                acc[i][2] + bb[2], acc[i][3] + bb[3]);
        float4 o1 = make_float4(acc[i][4] + bb[4], acc[i][5] + bb[5],
                                acc[i][6] + bb[6], acc[i][7] + bb[7]);
        *(float4*)&Cp[0] = o0;
        *(float4*)&Cp[4] = o1;
    }
}

// ---------------------------------------------------------------------------
// Per-head masked QK^T: qk[h][s][t] = (t<=s) ? q[h,s,:].k[h,t,:] : 0
// Only tiles intersecting the lower triangle are launched (bx<=by); the rest
// of g_qk stays zero (static init, never written).
// ---------------------------------------------------------------------------
__global__ __launch_bounds__(256)
void sgemm_qk()
{
    if (blockIdx.x > blockIdx.y) return;   // tile fully above diagonal
    const int h = blockIdx.z;
    const float* A = g_q + h * HDIM;                       // lda = D_MODEL
    const float* B = g_k + h * HDIM;                       // ldb = D_MODEL
    float* C = g_qk + (size_t)h * S_LEN * S_LEN;           // ldc = S_LEN

    __shared__ float As[8][128];
    __shared__ float Bs[8][128];
    const int tid  = threadIdx.x;
    const int tx   = tid & 15;
    const int ty   = tid >> 4;
    const int row0 = blockIdx.y << 7;   // s
    const int col0 = blockIdx.x << 7;   // t
    const int lrow = tid >> 1;
    const int lk   = (tid & 1) << 2;

    const float* Ap = A + (size_t)(row0 + lrow) * D_MODEL + lk;
    const float* Bp = B + (size_t)(col0 + lrow) * D_MODEL + lk;

    float acc[8][8];
#pragma unroll
    for (int i = 0; i < 8; i++)
#pragma unroll
        for (int j = 0; j < 8; j++) acc[i][j] = 0.f;

    for (int k0 = 0; k0 < HDIM; k0 += 8) {
        float4 av = *(const float4*)(Ap + k0);
        float4 bv = *(const float4*)(Bp + k0);
        As[lk + 0][lrow] = av.x; As[lk + 1][lrow] = av.y;
        As[lk + 2][lrow] = av.z; As[lk + 3][lrow] = av.w;
        Bs[lk + 0][lrow] = bv.x; Bs[lk + 1][lrow] = bv.y;
        Bs[lk + 2][lrow] = bv.z; Bs[lk + 3][lrow] = bv.w;
        __syncthreads();
#pragma unroll
        for (int kk = 0; kk < 8; kk++) {
            float a[8], b[8];
            *(float4*)&a[0] = *(const float4*)&As[kk][(ty << 3)];
            *(float4*)&a[4] = *(const float4*)&As[kk][(ty << 3) + 4];
            *(float4*)&b[0] = *(const float4*)&Bs[kk][(tx << 3)];
            *(float4*)&b[4] = *(const float4*)&Bs[kk][(tx << 3) + 4];
#pragma unroll
            for (int i = 0; i < 8; i++)
#pragma unroll
                for (int j = 0; j < 8; j++)
                    acc[i][j] = fmaf(a[i], b[j], acc[i][j]);
        }
        __syncthreads();
    }

#pragma unroll
    for (int i = 0; i < 8; i++) {
        const int r = row0 + (ty << 3) + i;
        float* Cp = C + (size_t)r * S_LEN + col0 + (tx << 3);
        float o[8];
#pragma unroll
        for (int j = 0; j < 8; j++) {
            const int cc = col0 + (tx << 3) + j;
            o[j] = (cc <= r) ? acc[i][j] : 0.f;
        }
        *(float4*)&Cp[0] = make_float4(o[0], o[1], o[2], o[3]);
        *(float4*)&Cp[4] = make_float4(o[4], o[5], o[6], o[7]);
    }
}

// ---------------------------------------------------------------------------
// Column logsumexp: L[h][t] = log( t * exp(0) + sum_{s>=t} exp(qk[h][s][t]/8) )
// Rows s < blockStart are all masked for every column in this block ->
// contribute exactly (float)blockStart; rows in [blockStart, t) read stored
// zeros so exp(0)=1 falls out naturally.
// ---------------------------------------------------------------------------
__global__ __launch_bounds__(256)
void col_lse_kernel()
{
    const int h  = blockIdx.y;
    const int t  = (blockIdx.x << 8) + threadIdx.x;
    const int s0 = blockIdx.x << 8;
    const float* base = g_qk + (size_t)h * S_LEN * S_LEN + t;

    float a0 = 0.f, a1 = 0.f, a2 = 0.f, a3 = 0.f;
    for (int s = s0; s < S_LEN; s += 4) {
        float v0 = base[(size_t)(s + 0) * S_LEN];
        float v1 = base[(size_t)(s + 1) * S_LEN];
        float v2 = base[(size_t)(s + 2) * S_LEN];
        float v3 = base[(size_t)(s + 3) * S_LEN];
        a0 += expf(v0 * 0.125f);
        a1 += expf(v1 * 0.125f);
        a2 += expf(v2 * 0.125f);
        a3 += expf(v3 * 0.125f);
    }
    g_L[h * S_LEN + t] = logf((float)s0 + ((a0 + a1) + (a2 + a3)));
}

// ---------------------------------------------------------------------------
// c[h][v] = sum_t L[h][t] * v[h][t][v]
// ---------------------------------------------------------------------------
__global__ __launch_bounds__(256)
void compute_c_kernel()
{
    __shared__ float part[4][HDIM];
    const int h = blockIdx.x;
    const int v = threadIdx.x & 63;
    const int g = threadIdx.x >> 6;   // 0..3
    const float* Lh = g_L + h * S_LEN;
    const float* vb = g_v + h * HDIM + v;
    float sum = 0.f;
    const int t0 = g * (S_LEN / 4);
    for (int t = t0; t < t0 + S_LEN / 4; t++)
        sum = fmaf(Lh[t], vb[(size_t)t * D_MODEL], sum);
    part[g][v] = sum;
    __syncthreads();
    if (g == 0)
        g_c[h * HDIM + v] = (part[0][v] + part[1][v]) + (part[2][v] + part[3][v]);
}

// ---------------------------------------------------------------------------
// Per-head attn: Z[s, h*64+v] = 0.125 * sum_{t<=s} qk[h][s][t]*v[h][t][v] - c[h][v]
// NN GEMM (B is [t][v], v contiguous). K-loop bounded at the diagonal block end.
// BM=128, BN=64, BK=8, 256 threads, 8x4 per thread.
// ---------------------------------------------------------------------------
__global__ __launch_bounds__(256)
void sgemm_attn()
{
    const int h    = blockIdx.y;
    const int row0 = blockIdx.x << 7;
    const float* A = g_qk + (size_t)h * S_LEN * S_LEN;  // lda = S_LEN
    const float* B = g_v + h * HDIM;                    // ldb = D_MODEL (NN)

    __shared__ float As[8][128];
    __shared__ float Bs[8][HDIM];
    const int tid  = threadIdx.x;
    const int tx   = tid & 15;          // 16 col groups * 4 = 64
    const int ty   = tid >> 4;          // 16 row groups * 8 = 128
    const int lrow = tid >> 1;
    const int lk   = (tid & 1) << 2;
    const int brow = tid >> 5;          // 0..7
    const int bcol = (tid & 31) << 1;   // 0..62

    float acc[8][4];
#pragma unroll
    for (int i = 0; i < 8; i++)
#pragma unroll
        for (int j = 0; j < 4; j++) acc[i][j] = 0.f;

    const int Kend = row0 + 128;        // only t <= s needed (zeros above diag)
    for (int k0 = 0; k0 < Kend; k0 += 8) {
        float4 av = *(const float4*)&A[(size_t)(row0 + lrow) * S_LEN + k0 + lk];
        float2 bv = *(const float2*)&B[(size_t)(k0 + brow) * D_MODEL + bcol];
        As[lk + 0][lrow] = av.x; As[lk + 1][lrow] = av.y;
        As[lk + 2][lrow] = av.z; As[lk + 3][lrow] = av.w;
        *(float2*)&Bs[brow][bcol] = bv;
        __syncthreads();
#pragma unroll
        for (int kk = 0; kk < 8; kk++) {
            float a[8], b[4];
            *(float4*)&a[0] = *(const float4*)&As[kk][(ty << 3)];
            *(float4*)&a[4] = *(const float4*)&As[kk][(ty << 3) + 4];
            *(float4*)&b[0] = *(const float4*)&Bs[kk][(tx << 2)];
#pragma unroll
            for (int i = 0; i < 8; i++)
#pragma unroll
                for (int j = 0; j < 4; j++)
                    acc[i][j] = fmaf(a[i], b[j], acc[i][j]);
        }
        __syncthreads();
    }

    float cv[4];
    *(float4*)&cv[0] = *(const float4*)&g_c[h * HDIM + (tx << 2)];
#pragma unroll
    for (int i = 0; i < 8; i++) {
        float* Cp = g_z + (size_t)(row0 + (ty << 3) + i) * D_MODEL + h * HDIM + (tx << 2);
        *(float4*)Cp = make_float4(acc[i][0] * 0.125f - cv[0],
                                   acc[i][1] * 0.125f - cv[1],
                                   acc[i][2] * 0.125f - cv[2],
                                   acc[i][3] * 0.125f - cv[3]);
    }
}

// ---------------------------------------------------------------------------
extern "C" void kernel_launch(void* const* d_in, const int* in_sizes, int n_in,
                              void* d_out, int out_size)
{
    const float* Qin = (const float*)d_in[0];
    const float* Kin = (const float*)d_in[1];
    const float* Vin = (const float*)d_in[2];
    const float* WQw = (const float*)d_in[3];
    const float* WQb = (const float*)d_in[4];
    const float* WKw = (const float*)d_in[5];
    const float* WKb = (const float*)d_in[6];
    const float* WVw = (const float*)d_in[7];
    const float* WVb = (const float*)d_in[8];
    const float* WOw = (const float*)d_in[9];
    const float* WOb = (const float*)d_in[10];
    float* Out = (float*)d_out;

    float *qp, *kp, *vp, *zp;
    cudaGetSymbolAddress((void**)&qp, g_q);
    cudaGetSymbolAddress((void**)&kp, g_k);
    cudaGetSymbolAddress((void**)&vp, g_v);
    cudaGetSymbolAddress((void**)&zp, g_z);

    dim3 blk(256);

    // 1) Q/K/V projections: [2048,1024] @ [1024,1024]^T + bias
    dim3 gproj(D_MODEL / 128, S_LEN / 128);
    sgemm_nt_bias<<<gproj, blk>>>(Qin, WQw, WQb, qp, D_MODEL, D_MODEL, D_MODEL, D_MODEL);
    sgemm_nt_bias<<<gproj, blk>>>(Kin, WKw, WKb, kp, D_MODEL, D_MODEL, D_MODEL, D_MODEL);
    sgemm_nt_bias<<<gproj, blk>>>(Vin, WVw, WVb, vp, D_MODEL, D_MODEL, D_MODEL, D_MODEL);

    // 2) masked QK^T per head (lower-triangle tiles only)
    dim3 gqk(S_LEN / 128, S_LEN / 128, NHEAD);
    sgemm_qk<<<gqk, blk>>>();

    // 3) per-column logsumexp -> L
    dim3 glse(S_LEN / 256, NHEAD);
    col_lse_kernel<<<glse, blk>>>();

    // 4) c = L^T V per head
    compute_c_kernel<<<NHEAD, blk>>>();

    // 5) attn = 0.125 * tril(QK) @ V - c  -> Z (head-major concat layout)
    dim3 gattn(S_LEN / 128, NHEAD);
    sgemm_attn<<<gattn, blk>>>();

    // 6) output projection: Z @ WOw^T + WOb
    dim3 gout(D_MODEL / 128, S_LEN / 128);
    sgemm_nt_bias<<<gout, blk>>>(zp, WOw, WOb, Out, D_MODEL, D_MODEL, D_MODEL, D_MODEL);
}